// round 8
// baseline (speedup 1.0000x reference)
#include <cuda_runtime.h>
#include <cuda_bf16.h>
#include <math.h>

// Problem constants  (reference: V, E, H, T = 32000, 512, 1024, 4096)
#define VSZ 32000
#define ESZ 512              // <-- E = 512 (was wrongly 1024 in rounds 0-7)
#define HSZ 1024
#define TSZ 4096
#define G4H 4096             // 4*H

// ---------------- scratch (device globals; no allocations) ----------------
__device__ float g_Xenc[(size_t)TSZ * G4H];        // 64 MB
__device__ float g_Xdec[(size_t)(TSZ - 1) * G4H];  // 64 MB
__device__ float g_hs[(size_t)(TSZ - 1) * HSZ];    // 16 MB
__device__ float g_h[2][HSZ];
__device__ float g_c[HSZ];
__device__ unsigned g_bar;

// ---------------- init: zero h/c state + barrier (pointer-based) ----------
__global__ void init_kernel(float* h0, float* h1, float* c, unsigned* bar) {
    int tid = blockIdx.x * blockDim.x + threadIdx.x;
    if (tid == 0) *bar = 0u;
    if (tid < HSZ) { h0[tid] = 0.f; h1[tid] = 0.f; c[tid] = 0.f; }
}

// ---------------- SGEMM (C = A_gathered * B^T + b1 [+ b2]) ----------------
// A: [?, K] row-major, row m taken from A[idx[m]] if idx else A[m]
// B: [N, K] row-major  (NT gemm); C: [M, N] row-major.  K % 8 == 0.
#define BM 128
#define BN 128
#define BK 8
__global__ __launch_bounds__(256) void gemm_nt_bias(
    const float* __restrict__ A, const int* __restrict__ idx,
    const float* __restrict__ B,
    const float* __restrict__ b1, const float* __restrict__ b2,
    float* __restrict__ C, int M, int N, int K)
{
    __shared__ float As[BK][BM];
    __shared__ float Bs[BK][BN];

    const int bm = blockIdx.y * BM;
    const int bn = blockIdx.x * BN;
    const int tid = threadIdx.x;
    const int tx = tid & 15;
    const int ty = tid >> 4;

    const int a_row = tid >> 1;
    const int a_c4  = (tid & 1) * 4;

    float acc[8][8];
#pragma unroll
    for (int i = 0; i < 8; i++)
#pragma unroll
        for (int j = 0; j < 8; j++) acc[i][j] = 0.f;

    for (int k0 = 0; k0 < K; k0 += BK) {
        float4 av = make_float4(0.f, 0.f, 0.f, 0.f);
        int gm = bm + a_row;
        if (gm < M) {
            int r = idx ? idx[gm] : gm;
            av = *(const float4*)(A + (size_t)r * K + k0 + a_c4);
        }
        As[a_c4 + 0][a_row] = av.x;
        As[a_c4 + 1][a_row] = av.y;
        As[a_c4 + 2][a_row] = av.z;
        As[a_c4 + 3][a_row] = av.w;

        int gn = bn + a_row;
        float4 bv = *(const float4*)(B + (size_t)gn * K + k0 + a_c4);
        Bs[a_c4 + 0][a_row] = bv.x;
        Bs[a_c4 + 1][a_row] = bv.y;
        Bs[a_c4 + 2][a_row] = bv.z;
        Bs[a_c4 + 3][a_row] = bv.w;

        __syncthreads();

#pragma unroll
        for (int k = 0; k < BK; k++) {
            float ra[8], rb[8];
            *(float4*)(ra)     = *(const float4*)&As[k][ty * 8];
            *(float4*)(ra + 4) = *(const float4*)&As[k][ty * 8 + 4];
            *(float4*)(rb)     = *(const float4*)&Bs[k][tx * 8];
            *(float4*)(rb + 4) = *(const float4*)&Bs[k][tx * 8 + 4];
#pragma unroll
            for (int i = 0; i < 8; i++)
#pragma unroll
                for (int j = 0; j < 8; j++)
                    acc[i][j] = fmaf(ra[i], rb[j], acc[i][j]);
        }
        __syncthreads();
    }

#pragma unroll
    for (int i = 0; i < 8; i++) {
        int m = bm + ty * 8 + i;
        if (m >= M) break;
        float* crow = C + (size_t)m * N + bn + tx * 8;
#pragma unroll
        for (int j = 0; j < 8; j++) {
            int n = bn + tx * 8 + j;
            float v = acc[i][j] + b1[n];
            if (b2) v += b2[n];
            crow[j] = v;
        }
    }
}

// ---------------- chunked persistent LSTM recurrence ----------------
// Block b owns hidden units 8b..8b+7 (32 gate rows). Row lr = tid>>3,
// contiguous segment seg = tid&7 (128 h-elems each). Whh streamed from L2.
// Grid barrier: monotonic counter, release = per-writer __threadfence after
// __stcg h store; acquire = __threadfence after spin; h read via __ldcv.
#define RB 128
#define RT 256

__device__ __forceinline__ float sigmoidf_acc(float x) {
    return 1.f / (1.f + expf(-x));
}

__global__ __launch_bounds__(RT) void lstm_chunk(
    const float* __restrict__ encW, const float* __restrict__ decW,
    const float* __restrict__ Xe,   const float* __restrict__ Xd,
    float* hbuf, float* __restrict__ c, float* __restrict__ hs,
    unsigned* bar, int gs0, int gs1)
{
    __shared__ __align__(16) float hsm[HSZ];
    __shared__ float part[RT];
    __shared__ float dsum[32];

    const int tid = threadIdx.x;
    const int u0  = blockIdx.x * 8;
    const int lr  = tid >> 3;
    const int seg = tid & 7;
    const int grow = (lr >> 3) * HSZ + u0 + (lr & 7);   // q*H + u

    for (int gs = gs0; gs < gs1; ++gs) {
        const bool enc = gs < TSZ;
        const float* W    = enc ? encW : decW;
        const int    s    = enc ? gs : gs - TSZ;
        const float* Xrow = (enc ? Xe : Xd) + (size_t)s * G4H;
        const float* hin  = hbuf + (gs & 1) * HSZ;
        float*       hout = hbuf + ((gs & 1) ^ 1) * HSZ;

        for (int i = tid; i < HSZ; i += RT) hsm[i] = __ldcv(hin + i);
        __syncthreads();

        const float4* w4 = (const float4*)(W + (size_t)grow * HSZ) + seg * 32;
        const float4* h4 = (const float4*)hsm + seg * 32;
        float sacc = 0.f;
#pragma unroll
        for (int k = 0; k < 32; ++k) {
            float4 wv = __ldg(w4 + k);
            float4 hv = h4[k];
            sacc = fmaf(wv.x, hv.x, sacc);
            sacc = fmaf(wv.y, hv.y, sacc);
            sacc = fmaf(wv.z, hv.z, sacc);
            sacc = fmaf(wv.w, hv.w, sacc);
        }
        part[tid] = sacc;
        __syncthreads();

        if (tid < 32) {
            float a = 0.f;
#pragma unroll
            for (int j = 0; j < 8; j++) a += part[tid * 8 + j];
            dsum[tid] = a;
        }
        __syncthreads();

        if (tid < 8) {
            const int u = u0 + tid;
            float gi = dsum[tid]      + Xrow[u];
            float gf = dsum[8 + tid]  + Xrow[HSZ + u];
            float gg = dsum[16 + tid] + Xrow[2 * HSZ + u];
            float go = dsum[24 + tid] + Xrow[3 * HSZ + u];
            gi = sigmoidf_acc(gi);
            gf = sigmoidf_acc(gf);
            gg = tanhf(gg);
            go = sigmoidf_acc(go);
            float cc = c[u];                 // block-private
            cc = fmaf(gf, cc, gi * gg);
            c[u] = cc;
            float h = go * tanhf(cc);
            __stcg(hout + u, h);
            if (!enc) hs[(size_t)s * HSZ + u] = h;
            __threadfence();                 // RELEASE
        }
        __syncthreads();

        if (tid == 0) {
            atomicAdd(bar, 1u);
            const unsigned target = (unsigned)(gs + 1) * RB;
            while (*((volatile unsigned*)bar) < target) { }
            __threadfence();                 // ACQUIRE
        }
        __syncthreads();
    }
}

// ---------------- launch ----------------
extern "C" void kernel_launch(void* const* d_in, const int* in_sizes, int n_in,
                              void* d_out, int out_size)
{
    const int*   seq     = (const int*)  d_in[0];
    const float* enc_emb = (const float*)d_in[1];   // [V, E=512]
    const float* enc_Wih = (const float*)d_in[2];   // [4H, E=512]
    const float* enc_Whh = (const float*)d_in[3];   // [4H, H=1024]
    const float* enc_bih = (const float*)d_in[4];
    const float* enc_bhh = (const float*)d_in[5];
    const float* dec_emb = (const float*)d_in[6];
    const float* dec_Wih = (const float*)d_in[7];
    const float* dec_Whh = (const float*)d_in[8];
    const float* dec_bih = (const float*)d_in[9];
    const float* dec_bhh = (const float*)d_in[10];
    const float* out_W   = (const float*)d_in[11];  // [V, H]
    const float* out_b   = (const float*)d_in[12];
    float* out = (float*)d_out;

    void *pXenc = nullptr, *pXdec = nullptr, *phs = nullptr,
         *ph = nullptr, *pc = nullptr, *pbar = nullptr;
    cudaGetSymbolAddress(&pXenc, g_Xenc);
    cudaGetSymbolAddress(&pXdec, g_Xdec);
    cudaGetSymbolAddress(&phs,  g_hs);
    cudaGetSymbolAddress(&ph,   g_h);
    cudaGetSymbolAddress(&pc,   g_c);
    cudaGetSymbolAddress(&pbar, g_bar);

    float* Xe   = (float*)pXenc;
    float* Xd   = (float*)pXdec;
    float* hs   = (float*)phs;
    float* hbuf = (float*)ph;
    float* cst  = (float*)pc;
    unsigned* bar = (unsigned*)pbar;

    // 0) reset state every launch (graph-replay safe)
    init_kernel<<<4, 256>>>(hbuf, hbuf + HSZ, cst, bar);

    // 1) encoder input projection: Xenc[t] = enc_Wih @ emb[seq[t]] + bih + bhh
    {
        dim3 grid(G4H / BN, (TSZ + BM - 1) / BM);
        gemm_nt_bias<<<grid, 256>>>(enc_emb, seq, enc_Wih, enc_bih, enc_bhh,
                                    Xe, TSZ, G4H, ESZ);
    }
    // 2) decoder input projection (seq[:-1])
    {
        dim3 grid(G4H / BN, (TSZ - 1 + BM - 1) / BM);
        gemm_nt_bias<<<grid, 256>>>(dec_emb, seq, dec_Wih, dec_bih, dec_bhh,
                                    Xd, TSZ - 1, G4H, ESZ);
    }

    // 3) recurrence: 8 chunked persistent launches over steps [0, 8191)
    const int total_steps = TSZ + (TSZ - 1);   // 8191
    const int CHUNK = 1024;
    for (int gs0 = 0; gs0 < total_steps; gs0 += CHUNK) {
        int gs1 = gs0 + CHUNK;
        if (gs1 > total_steps) gs1 = total_steps;
        lstm_chunk<<<RB, RT>>>(enc_Whh, dec_Whh, Xe, Xd,
                               hbuf, cst, hs, bar, gs0, gs1);
    }

    // 4) logits = hs @ out_W^T + out_b  -> d_out [4095, 1, 32000]
    {
        dim3 grid(VSZ / BN, (TSZ - 1 + BM - 1) / BM);
        gemm_nt_bias<<<grid, 256>>>(hs, nullptr, out_W,
                                    out_b, nullptr, out, TSZ - 1, VSZ, HSZ);
    }
}

// round 9
// speedup vs baseline: 1.3550x; 1.3550x over previous
#include <cuda_runtime.h>
#include <cuda_bf16.h>
#include <math.h>

// Problem constants  (V, E, H, T = 32000, 512, 1024, 4096)
#define VSZ 32000
#define ESZ 512
#define HSZ 1024
#define TSZ 4096
#define G4H 4096             // 4*H

// ---------------- scratch (device globals; no allocations) ----------------
__device__ float g_Xenc[(size_t)TSZ * G4H];        // 64 MB
__device__ float g_Xdec[(size_t)(TSZ - 1) * G4H];  // 64 MB
__device__ float g_hs[(size_t)(TSZ - 1) * HSZ];    // 16 MB
__device__ float g_h[2][HSZ];
__device__ float g_c[HSZ];
__device__ unsigned g_flags[128 * 8];              // padded: flag b at [b*8]

// ---------------- init: zero h/c state + flags ----------
__global__ void init_kernel(float* h0, float* h1, float* c, unsigned* flags) {
    int tid = blockIdx.x * blockDim.x + threadIdx.x;
    if (tid < 128 * 8) flags[tid] = 0u;
    if (tid < HSZ) { h0[tid] = 0.f; h1[tid] = 0.f; c[tid] = 0.f; }
}

// ---------------- SGEMM (C = A_gathered * B^T + bias1 [+ bias2]) ----------
// A: [?, K] row-major, row m from A[idx[m]] if idx else A[m]
// B: [N, K] row-major (NT); C: [M, N] row-major.  K%16==0, N%128==0.
#define BM 128
#define BN 128
#define BK 16
__global__ __launch_bounds__(256) void gemm_nt_bias(
    const float* __restrict__ A, const int* __restrict__ idx,
    const float* __restrict__ B,
    const float* __restrict__ bias1, const float* __restrict__ bias2,
    float* __restrict__ C, int M, int N, int K)
{
    __shared__ float As[BK][BM];
    __shared__ float Bs[BK][BN];

    const int bm = blockIdx.y * BM;
    const int bn = blockIdx.x * BN;
    const int tid = threadIdx.x;
    const int tx = tid & 15;          // col fragment selector
    const int ty = tid >> 4;          // row fragment selector

    const int lrow = tid >> 1;        // 0..127 tile row loaded by this thread
    const int lk   = (tid & 1) * 8;   // k-offset 0 or 8 (two float4 each)

    const int gm = bm + lrow;
    const bool am = (gm < M);
    const int ar = am ? (idx ? idx[gm] : gm) : 0;
    const float* Arow = A + (size_t)ar * K;
    const float* Brow = B + (size_t)(bn + lrow) * K;

    float4 la0, la1, lb0, lb1;
    const float4 z4 = make_float4(0.f, 0.f, 0.f, 0.f);
    // prefetch tile 0
    la0 = am ? *(const float4*)(Arow + lk)     : z4;
    la1 = am ? *(const float4*)(Arow + lk + 4) : z4;
    lb0 = *(const float4*)(Brow + lk);
    lb1 = *(const float4*)(Brow + lk + 4);

    float acc[8][8];
#pragma unroll
    for (int i = 0; i < 8; i++)
#pragma unroll
        for (int j = 0; j < 8; j++) acc[i][j] = 0.f;

    for (int k0 = 0; k0 < K; k0 += BK) {
        // commit prefetched tile to smem (transposed)
        As[lk + 0][lrow] = la0.x; As[lk + 1][lrow] = la0.y;
        As[lk + 2][lrow] = la0.z; As[lk + 3][lrow] = la0.w;
        As[lk + 4][lrow] = la1.x; As[lk + 5][lrow] = la1.y;
        As[lk + 6][lrow] = la1.z; As[lk + 7][lrow] = la1.w;
        Bs[lk + 0][lrow] = lb0.x; Bs[lk + 1][lrow] = lb0.y;
        Bs[lk + 2][lrow] = lb0.z; Bs[lk + 3][lrow] = lb0.w;
        Bs[lk + 4][lrow] = lb1.x; Bs[lk + 5][lrow] = lb1.y;
        Bs[lk + 6][lrow] = lb1.z; Bs[lk + 7][lrow] = lb1.w;
        __syncthreads();

        // prefetch next tile (overlaps with compute below)
        if (k0 + BK < K) {
            const int ko = k0 + BK + lk;
            la0 = am ? *(const float4*)(Arow + ko)     : z4;
            la1 = am ? *(const float4*)(Arow + ko + 4) : z4;
            lb0 = *(const float4*)(Brow + ko);
            lb1 = *(const float4*)(Brow + ko + 4);
        }

#pragma unroll
        for (int k = 0; k < BK; k++) {
            float ra[8], rb[8];
            *(float4*)(ra)     = *(const float4*)&As[k][ty * 4];
            *(float4*)(ra + 4) = *(const float4*)&As[k][64 + ty * 4];
            *(float4*)(rb)     = *(const float4*)&Bs[k][tx * 4];
            *(float4*)(rb + 4) = *(const float4*)&Bs[k][64 + tx * 4];
#pragma unroll
            for (int i = 0; i < 8; i++)
#pragma unroll
                for (int j = 0; j < 8; j++)
                    acc[i][j] = fmaf(ra[i], rb[j], acc[i][j]);
        }
        __syncthreads();
    }

    // epilogue: rows {ty*4+i, 64+ty*4+i}, cols {tx*4+j, 64+tx*4+j}
#pragma unroll
    for (int i = 0; i < 8; i++) {
        const int m = bm + ((i < 4) ? (ty * 4 + i) : (64 + ty * 4 + i - 4));
        if (m >= M) continue;
#pragma unroll
        for (int j = 0; j < 8; j++) {
            const int n = bn + ((j < 4) ? (tx * 4 + j) : (64 + tx * 4 + j - 4));
            float v = acc[i][j] + bias1[n];
            if (bias2) v += bias2[n];
            C[(size_t)m * N + n] = v;
        }
    }
}

// ---------------- chunked persistent LSTM (weights in registers) ----------
// 128 blocks x 256 threads. Block b owns units 8b..8b+7 (32 gate rows).
// Thread (lr=tid>>3, seg=tid&7) holds W[grow][seg*128..+128) in 32 float4 regs
// for the whole chunk. Per step: stage h, 128 reg-FMA, shfl-reduce by 8,
// gates on tid<8, distributed flag barrier (no same-address atomics).
#define RB 128
#define RT 256

__device__ __forceinline__ float sigmoidf_acc(float x) {
    return 1.f / (1.f + expf(-x));
}

__global__ __launch_bounds__(RT) void lstm_chunk(
    const float* __restrict__ encW, const float* __restrict__ decW,
    const float* __restrict__ Xe,   const float* __restrict__ Xd,
    float* hbuf, float* __restrict__ c, float* __restrict__ hs,
    unsigned* flags, int gs0, int gs1)
{
    __shared__ __align__(16) float hsm[HSZ];
    __shared__ float dsum[32];

    const int tid = threadIdx.x;
    const int u0  = blockIdx.x * 8;
    const int lr  = tid >> 3;                 // 0..31 local gate-row
    const int seg = tid & 7;                  // 0..7 (128 h-elems each)
    const int grow = (lr >> 3) * HSZ + u0 + (lr & 7);   // q*H + u

    // chunk is entirely one phase (4096 % 1024 == 0)
    const bool encPhase = (gs0 < TSZ);
    const float* W  = encPhase ? encW : decW;
    const float* Xb = encPhase ? Xe : Xd;

    // load this thread's weight slice into registers (once per chunk)
    float4 wreg[32];
    {
        const float4* wsrc = (const float4*)(W + (size_t)grow * HSZ) + seg * 32;
#pragma unroll
        for (int k = 0; k < 32; k++) wreg[k] = __ldg(wsrc + k);
    }

    // cell state for unit u0+tid (tid<8), persisted across chunks in global
    float creg = (tid < 8) ? c[u0 + tid] : 0.f;

    for (int gs = gs0; gs < gs1; ++gs) {
        const int s = encPhase ? gs : gs - TSZ;
        const float* Xrow = Xb + (size_t)s * G4H;
        const float* hin  = hbuf + (gs & 1) * HSZ;
        float*       hout = hbuf + ((gs & 1) ^ 1) * HSZ;

        // stage h from L2 (other SMs wrote it)
        for (int i = tid; i < HSZ; i += RT) hsm[i] = __ldcv(hin + i);

        // prefetch this step's X gate biases early (independent of hsm)
        float x0 = 0.f, x1 = 0.f, x2 = 0.f, x3 = 0.f;
        if (tid < 8) {
            const int u = u0 + tid;
            x0 = __ldg(Xrow + u);
            x1 = __ldg(Xrow + HSZ + u);
            x2 = __ldg(Xrow + 2 * HSZ + u);
            x3 = __ldg(Xrow + 3 * HSZ + u);
        }
        __syncthreads();

        // dot: this thread's 128-elem segment of its gate row
        const float4* h4 = (const float4*)hsm + seg * 32;
        float acc = 0.f;
#pragma unroll
        for (int k = 0; k < 32; ++k) {
            const float4 hv = h4[k];
            acc = fmaf(wreg[k].x, hv.x, acc);
            acc = fmaf(wreg[k].y, hv.y, acc);
            acc = fmaf(wreg[k].z, hv.z, acc);
            acc = fmaf(wreg[k].w, hv.w, acc);
        }
        // reduce across the 8 segments (consecutive lanes)
        acc += __shfl_down_sync(0xffffffffu, acc, 4, 8);
        acc += __shfl_down_sync(0xffffffffu, acc, 2, 8);
        acc += __shfl_down_sync(0xffffffffu, acc, 1, 8);
        if (seg == 0) dsum[lr] = acc;
        __syncthreads();

        if (tid < 8) {
            const int u = u0 + tid;
            const float gi = sigmoidf_acc(dsum[tid]      + x0);
            const float gf = sigmoidf_acc(dsum[8 + tid]  + x1);
            const float gg = tanhf(dsum[16 + tid] + x2);
            const float go = sigmoidf_acc(dsum[24 + tid] + x3);
            creg = fmaf(gf, creg, gi * gg);
            const float h = go * tanhf(creg);
            __stcg(hout + u, h);
            if (!encPhase) hs[(size_t)s * HSZ + u] = h;
            __threadfence();                  // RELEASE h before flag
        }
        __syncthreads();

        // distributed flag barrier: block signs its padded flag; thread i
        // waits only on block i's flag (no shared-address contention).
        if (tid == 0) __stcg(&flags[blockIdx.x * 8], (unsigned)(gs + 1));
        if (tid < RB) {
            const unsigned target = (unsigned)(gs + 1);
            while (*((volatile unsigned*)&flags[tid * 8]) < target) { }
        }
        __syncthreads();
        if (tid == 0) __threadfence();        // ACQUIRE before next h read
        __syncthreads();
    }

    if (tid < 8) c[u0 + tid] = creg;          // persist cell state
}

// ---------------- launch ----------------
extern "C" void kernel_launch(void* const* d_in, const int* in_sizes, int n_in,
                              void* d_out, int out_size)
{
    const int*   seq     = (const int*)  d_in[0];
    const float* enc_emb = (const float*)d_in[1];   // [V, 512]
    const float* enc_Wih = (const float*)d_in[2];   // [4H, 512]
    const float* enc_Whh = (const float*)d_in[3];   // [4H, 1024]
    const float* enc_bih = (const float*)d_in[4];
    const float* enc_bhh = (const float*)d_in[5];
    const float* dec_emb = (const float*)d_in[6];
    const float* dec_Wih = (const float*)d_in[7];
    const float* dec_Whh = (const float*)d_in[8];
    const float* dec_bih = (const float*)d_in[9];
    const float* dec_bhh = (const float*)d_in[10];
    const float* out_W   = (const float*)d_in[11];  // [V, H]
    const float* out_b   = (const float*)d_in[12];
    float* out = (float*)d_out;

    void *pXenc = nullptr, *pXdec = nullptr, *phs = nullptr,
         *ph = nullptr, *pc = nullptr, *pflags = nullptr;
    cudaGetSymbolAddress(&pXenc, g_Xenc);
    cudaGetSymbolAddress(&pXdec, g_Xdec);
    cudaGetSymbolAddress(&phs,  g_hs);
    cudaGetSymbolAddress(&ph,   g_h);
    cudaGetSymbolAddress(&pc,   g_c);
    cudaGetSymbolAddress(&pflags, g_flags);

    float* Xe   = (float*)pXenc;
    float* Xd   = (float*)pXdec;
    float* hs   = (float*)phs;
    float* hbuf = (float*)ph;
    float* cst  = (float*)pc;
    unsigned* flags = (unsigned*)pflags;

    // 0) reset state every launch (graph-replay safe)
    init_kernel<<<4, 256>>>(hbuf, hbuf + HSZ, cst, flags);

    // 1) encoder input projection: Xenc[t] = enc_Wih @ emb[seq[t]] + bih + bhh
    {
        dim3 grid(G4H / BN, (TSZ + BM - 1) / BM);
        gemm_nt_bias<<<grid, 256>>>(enc_emb, seq, enc_Wih, enc_bih, enc_bhh,
                                    Xe, TSZ, G4H, ESZ);
    }
    // 2) decoder input projection (seq[:-1])
    {
        dim3 grid(G4H / BN, (TSZ - 1 + BM - 1) / BM);
        gemm_nt_bias<<<grid, 256>>>(dec_emb, seq, dec_Wih, dec_bih, dec_bhh,
                                    Xd, TSZ - 1, G4H, ESZ);
    }

    // 3) recurrence: 8 chunked persistent launches (each chunk single-phase)
    const int total_steps = TSZ + (TSZ - 1);   // 8191
    const int CHUNK = 1024;
    for (int gs0 = 0; gs0 < total_steps; gs0 += CHUNK) {
        int gs1 = gs0 + CHUNK;
        if (gs1 > total_steps) gs1 = total_steps;
        lstm_chunk<<<RB, RT>>>(enc_Whh, dec_Whh, Xe, Xd,
                               hbuf, cst, hs, flags, gs0, gs1);
    }

    // 4) logits = hs @ out_W^T + out_b  -> d_out [4095, 1, 32000]
    {
        dim3 grid(VSZ / BN, (TSZ - 1 + BM - 1) / BM);
        gemm_nt_bias<<<grid, 256>>>(hs, nullptr, out_W,
                                    out_b, nullptr, out, TSZ - 1, VSZ, HSZ);
    }
}

// round 10
// speedup vs baseline: 2.6026x; 1.9207x over previous
#include <cuda_runtime.h>
#include <cuda_bf16.h>
#include <math.h>

// Problem constants  (V, E, H, T = 32000, 512, 1024, 4096)
#define VSZ 32000
#define ESZ 512
#define HSZ 1024
#define TSZ 4096
#define G4H 4096             // 4*H

// ---------------- scratch (device globals; no allocations) ----------------
__device__ float g_Xenc[(size_t)TSZ * G4H];        // 64 MB
__device__ float g_Xdec[(size_t)(TSZ - 1) * G4H];  // 64 MB
__device__ float g_hs[(size_t)(TSZ - 1) * HSZ];    // 16 MB
__device__ float g_h[2][HSZ];
__device__ float g_c[HSZ];
__device__ unsigned g_flags[128 * 8];              // padded: flag b at [b*8]

// ---------------- init: zero h/c state + flags ----------
__global__ void init_kernel(float* h0, float* h1, float* c, unsigned* flags) {
    int tid = blockIdx.x * blockDim.x + threadIdx.x;
    if (tid < 128 * 8) flags[tid] = 0u;
    if (tid < HSZ) { h0[tid] = 0.f; h1[tid] = 0.f; c[tid] = 0.f; }
}

// ---------------- SGEMM (C = A_gathered * B^T + bias1 [+ bias2]) ----------
#define BM 128
#define BN 128
#define BK 16
__global__ __launch_bounds__(256) void gemm_nt_bias(
    const float* __restrict__ A, const int* __restrict__ idx,
    const float* __restrict__ B,
    const float* __restrict__ bias1, const float* __restrict__ bias2,
    float* __restrict__ C, int M, int N, int K)
{
    __shared__ float As[BK][BM];
    __shared__ float Bs[BK][BN];

    const int bm = blockIdx.y * BM;
    const int bn = blockIdx.x * BN;
    const int tid = threadIdx.x;
    const int tx = tid & 15;
    const int ty = tid >> 4;

    const int lrow = tid >> 1;
    const int lk   = (tid & 1) * 8;

    const int gm = bm + lrow;
    const bool am = (gm < M);
    const int ar = am ? (idx ? idx[gm] : gm) : 0;
    const float* Arow = A + (size_t)ar * K;
    const float* Brow = B + (size_t)(bn + lrow) * K;

    float4 la0, la1, lb0, lb1;
    const float4 z4 = make_float4(0.f, 0.f, 0.f, 0.f);
    la0 = am ? *(const float4*)(Arow + lk)     : z4;
    la1 = am ? *(const float4*)(Arow + lk + 4) : z4;
    lb0 = *(const float4*)(Brow + lk);
    lb1 = *(const float4*)(Brow + lk + 4);

    float acc[8][8];
#pragma unroll
    for (int i = 0; i < 8; i++)
#pragma unroll
        for (int j = 0; j < 8; j++) acc[i][j] = 0.f;

    for (int k0 = 0; k0 < K; k0 += BK) {
        As[lk + 0][lrow] = la0.x; As[lk + 1][lrow] = la0.y;
        As[lk + 2][lrow] = la0.z; As[lk + 3][lrow] = la0.w;
        As[lk + 4][lrow] = la1.x; As[lk + 5][lrow] = la1.y;
        As[lk + 6][lrow] = la1.z; As[lk + 7][lrow] = la1.w;
        Bs[lk + 0][lrow] = lb0.x; Bs[lk + 1][lrow] = lb0.y;
        Bs[lk + 2][lrow] = lb0.z; Bs[lk + 3][lrow] = lb0.w;
        Bs[lk + 4][lrow] = lb1.x; Bs[lk + 5][lrow] = lb1.y;
        Bs[lk + 6][lrow] = lb1.z; Bs[lk + 7][lrow] = lb1.w;
        __syncthreads();

        if (k0 + BK < K) {
            const int ko = k0 + BK + lk;
            la0 = am ? *(const float4*)(Arow + ko)     : z4;
            la1 = am ? *(const float4*)(Arow + ko + 4) : z4;
            lb0 = *(const float4*)(Brow + ko);
            lb1 = *(const float4*)(Brow + ko + 4);
        }

#pragma unroll
        for (int k = 0; k < BK; k++) {
            float ra[8], rb[8];
            *(float4*)(ra)     = *(const float4*)&As[k][ty * 4];
            *(float4*)(ra + 4) = *(const float4*)&As[k][64 + ty * 4];
            *(float4*)(rb)     = *(const float4*)&Bs[k][tx * 4];
            *(float4*)(rb + 4) = *(const float4*)&Bs[k][64 + tx * 4];
#pragma unroll
            for (int i = 0; i < 8; i++)
#pragma unroll
                for (int j = 0; j < 8; j++)
                    acc[i][j] = fmaf(ra[i], rb[j], acc[i][j]);
        }
        __syncthreads();
    }

#pragma unroll
    for (int i = 0; i < 8; i++) {
        const int m = bm + ((i < 4) ? (ty * 4 + i) : (64 + ty * 4 + i - 4));
        if (m >= M) continue;
#pragma unroll
        for (int j = 0; j < 8; j++) {
            const int n = bn + ((j < 4) ? (tx * 4 + j) : (64 + tx * 4 + j - 4));
            float v = acc[i][j] + bias1[n];
            if (bias2) v += bias2[n];
            C[(size_t)m * N + n] = v;
        }
    }
}

// ---------------- chunked persistent LSTM (warp-per-segment) --------------
// 128 blocks x 256 threads. Block b owns units 8b..8b+7 (32 gate rows).
// Warp w owns h-segment [w*128, w*128+128); lane l owns gate row l.
// -> every LDS in the dot is a 32-lane broadcast: ZERO bank conflicts.
// Weights in registers (32 float4/thread). Cross-warp reduce via part[8][32].
// Flag barrier doubles as entry gate: own flag signed only after warp 0
// finishes the step, so no trailing __syncthreads needed.
#define RB 128
#define RT 256

__device__ __forceinline__ float sigmoidf_acc(float x) {
    return 1.f / (1.f + expf(-x));
}

__global__ __launch_bounds__(RT) void lstm_chunk(
    const float* __restrict__ encW, const float* __restrict__ decW,
    const float* __restrict__ Xe,   const float* __restrict__ Xd,
    float* hbuf, float* __restrict__ c, float* __restrict__ hs,
    unsigned* flags, int gs0, int gs1)
{
    __shared__ __align__(16) float4 hsm4[HSZ / 4];   // staged h (1024 floats)
    __shared__ float part[8 * 32];                   // per-warp row partials

    const int tid  = threadIdx.x;
    const int lane = tid & 31;
    const int wid  = tid >> 5;                // 0..7 = segment
    const int u0   = blockIdx.x * 8;
    // lane -> gate row: q = lane>>3 (gate), du = lane&7 (unit)
    const int grow = (lane >> 3) * HSZ + u0 + (lane & 7);

    const bool encPhase = (gs0 < TSZ);        // chunk is single-phase
    const float* W  = encPhase ? encW : decW;
    const float* Xb = encPhase ? Xe : Xd;

    // weight slice: row grow, columns [wid*128, wid*128+128) -> 32 float4
    float4 wreg[32];
    {
        const float4* wsrc = (const float4*)(W + (size_t)grow * HSZ) + wid * 32;
#pragma unroll
        for (int k = 0; k < 32; k++) wreg[k] = __ldg(wsrc + k);
    }

    const bool owner = (wid == 0 && lane < 8);    // unit owners (warp 0)
    float creg = owner ? c[u0 + lane] : 0.f;

    for (int gs = gs0; gs < gs1; ++gs) {
        const int s = encPhase ? gs : gs - TSZ;
        const float* Xrow = Xb + (size_t)s * G4H;
        const float4* hin4 = (const float4*)(hbuf + (gs & 1) * HSZ);
        float*        hout = hbuf + ((gs & 1) ^ 1) * HSZ;

        // entry barrier: wait until ALL blocks signed step gs (h_{gs-1} ready)
        if (tid < RB) {
            const unsigned target = (unsigned)gs;
            while (*((volatile unsigned*)&flags[tid * 8]) < target) { }
        }
        __syncthreads();

        // stage h: one float4 per thread, coalesced, L1-bypassing
        hsm4[tid] = __ldcv(hin4 + tid);

        // owners prefetch X gate biases (independent of hsm)
        float x0 = 0.f, x1 = 0.f, x2 = 0.f, x3 = 0.f;
        if (owner) {
            const int u = u0 + lane;
            x0 = __ldg(Xrow + u);
            x1 = __ldg(Xrow + HSZ + u);
            x2 = __ldg(Xrow + 2 * HSZ + u);
            x3 = __ldg(Xrow + 3 * HSZ + u);
        }
        __syncthreads();

        // dot: all lanes of warp `wid` read the SAME hseg[k] -> broadcast
        const float4* hseg = hsm4 + wid * 32;
        float a0 = 0.f, a1 = 0.f, a2 = 0.f, a3 = 0.f;
#pragma unroll
        for (int k = 0; k < 32; k += 4) {
            const float4 h0 = hseg[k],     h1 = hseg[k + 1];
            const float4 h2 = hseg[k + 2], h3 = hseg[k + 3];
            a0 = fmaf(wreg[k].x,     h0.x, a0); a0 = fmaf(wreg[k].y,     h0.y, a0);
            a0 = fmaf(wreg[k].z,     h0.z, a0); a0 = fmaf(wreg[k].w,     h0.w, a0);
            a1 = fmaf(wreg[k + 1].x, h1.x, a1); a1 = fmaf(wreg[k + 1].y, h1.y, a1);
            a1 = fmaf(wreg[k + 1].z, h1.z, a1); a1 = fmaf(wreg[k + 1].w, h1.w, a1);
            a2 = fmaf(wreg[k + 2].x, h2.x, a2); a2 = fmaf(wreg[k + 2].y, h2.y, a2);
            a2 = fmaf(wreg[k + 2].z, h2.z, a2); a2 = fmaf(wreg[k + 2].w, h2.w, a2);
            a3 = fmaf(wreg[k + 3].x, h3.x, a3); a3 = fmaf(wreg[k + 3].y, h3.y, a3);
            a3 = fmaf(wreg[k + 3].z, h3.z, a3); a3 = fmaf(wreg[k + 3].w, h3.w, a3);
        }
        part[wid * 32 + lane] = (a0 + a1) + (a2 + a3);
        __syncthreads();

        // warp 0: finish rows, gather gates per unit, update state, sign flag
        if (wid == 0) {
            float r = part[lane];
#pragma unroll
            for (int w = 1; w < 8; w++) r += part[w * 32 + lane];
            // r = full dot of gate row `lane`. Unit du needs rows du,8+du,16+du,24+du.
            const int du = lane & 7;
            const float vI = __shfl_sync(0xffffffffu, r, du);
            const float vF = __shfl_sync(0xffffffffu, r, du + 8);
            const float vG = __shfl_sync(0xffffffffu, r, du + 16);
            const float vO = __shfl_sync(0xffffffffu, r, du + 24);
            if (lane < 8) {
                const int u = u0 + lane;
                const float gi = sigmoidf_acc(vI + x0);
                const float gf = sigmoidf_acc(vF + x1);
                const float gg = tanhf(vG + x2);
                const float go = sigmoidf_acc(vO + x3);
                creg = fmaf(gf, creg, gi * gg);
                const float h = go * tanhf(creg);
                __stcg(hout + u, h);
                if (!encPhase) hs[(size_t)s * HSZ + u] = h;
                __threadfence();               // RELEASE h before flag
            }
            __syncwarp();
            if (lane == 0)
                __stcg(&flags[blockIdx.x * 8], (unsigned)(gs + 1));
        }
        // no trailing sync: next iteration's poll waits on own flag, which is
        // signed only after warp 0 completes; __syncthreads after poll re-joins.
    }

    if (owner) c[u0 + lane] = creg;           // persist cell state
}

// ---------------- launch ----------------
extern "C" void kernel_launch(void* const* d_in, const int* in_sizes, int n_in,
                              void* d_out, int out_size)
{
    const int*   seq     = (const int*)  d_in[0];
    const float* enc_emb = (const float*)d_in[1];   // [V, 512]
    const float* enc_Wih = (const float*)d_in[2];   // [4H, 512]
    const float* enc_Whh = (const float*)d_in[3];   // [4H, 1024]
    const float* enc_bih = (const float*)d_in[4];
    const float* enc_bhh = (const float*)d_in[5];
    const float* dec_emb = (const float*)d_in[6];
    const float* dec_Wih = (const float*)d_in[7];
    const float* dec_Whh = (const float*)d_in[8];
    const float* dec_bih = (const float*)d_in[9];
    const float* dec_bhh = (const float*)d_in[10];
    const float* out_W   = (const float*)d_in[11];  // [V, H]
    const float* out_b   = (const float*)d_in[12];
    float* out = (float*)d_out;

    void *pXenc = nullptr, *pXdec = nullptr, *phs = nullptr,
         *ph = nullptr, *pc = nullptr, *pflags = nullptr;
    cudaGetSymbolAddress(&pXenc, g_Xenc);
    cudaGetSymbolAddress(&pXdec, g_Xdec);
    cudaGetSymbolAddress(&phs,  g_hs);
    cudaGetSymbolAddress(&ph,   g_h);
    cudaGetSymbolAddress(&pc,   g_c);
    cudaGetSymbolAddress(&pflags, g_flags);

    float* Xe   = (float*)pXenc;
    float* Xd   = (float*)pXdec;
    float* hs   = (float*)phs;
    float* hbuf = (float*)ph;
    float* cst  = (float*)pc;
    unsigned* flags = (unsigned*)pflags;

    // 0) reset state every launch (graph-replay safe)
    init_kernel<<<4, 256>>>(hbuf, hbuf + HSZ, cst, flags);

    // 1) encoder input projection
    {
        dim3 grid(G4H / BN, (TSZ + BM - 1) / BM);
        gemm_nt_bias<<<grid, 256>>>(enc_emb, seq, enc_Wih, enc_bih, enc_bhh,
                                    Xe, TSZ, G4H, ESZ);
    }
    // 2) decoder input projection (seq[:-1])
    {
        dim3 grid(G4H / BN, (TSZ - 1 + BM - 1) / BM);
        gemm_nt_bias<<<grid, 256>>>(dec_emb, seq, dec_Wih, dec_bih, dec_bhh,
                                    Xd, TSZ - 1, G4H, ESZ);
    }

    // 3) recurrence: 8 chunked persistent launches (each chunk single-phase)
    const int total_steps = TSZ + (TSZ - 1);   // 8191
    const int CHUNK = 1024;
    for (int gs0 = 0; gs0 < total_steps; gs0 += CHUNK) {
        int gs1 = gs0 + CHUNK;
        if (gs1 > total_steps) gs1 = total_steps;
        lstm_chunk<<<RB, RT>>>(enc_Whh, dec_Whh, Xe, Xd,
                               hbuf, cst, hs, flags, gs0, gs1);
    }

    // 4) logits = hs @ out_W^T + out_b  -> d_out [4095, 1, 32000]
    {
        dim3 grid(VSZ / BN, (TSZ - 1 + BM - 1) / BM);
        gemm_nt_bias<<<grid, 256>>>(hs, nullptr, out_W,
                                    out_b, nullptr, out, TSZ - 1, VSZ, HSZ);
    }
}

// round 14
// speedup vs baseline: 2.9357x; 1.1280x over previous
#include <cuda_runtime.h>
#include <cuda_bf16.h>
#include <cuda_fp16.h>
#include <math.h>
#include <stdint.h>

// Problem constants  (V, E, H, T = 32000, 512, 1024, 4096)
#define VSZ 32000
#define ESZ 512
#define HSZ 1024
#define TSZ 4096
#define G4H 4096             // 4*H

// ---------------- scratch (device globals; no allocations) ----------------
__device__ float g_Xenc[(size_t)TSZ * G4H];        // 64 MB
__device__ float g_Xdec[(size_t)(TSZ - 1) * G4H];  // 64 MB
__device__ float g_hs[(size_t)(TSZ - 1) * HSZ];    // 16 MB
__device__ __half g_hsh[(size_t)(TSZ - 1) * HSZ];  // 8.4 MB fp16 hs
__device__ __half g_Wh [(size_t)VSZ * HSZ];        // 64 MB fp16 out_W
__device__ float g_h[2][HSZ];
__device__ float g_c[HSZ];
__device__ unsigned g_flags[128 * 8];              // padded: flag b at [b*8]

// ---------------- init: zero h/c state + flags ----------
__global__ void init_kernel(float* h0, float* h1, float* c, unsigned* flags) {
    int tid = blockIdx.x * blockDim.x + threadIdx.x;
    if (tid < 128 * 8) flags[tid] = 0u;
    if (tid < HSZ) { h0[tid] = 0.f; h1[tid] = 0.f; c[tid] = 0.f; }
}

// ---------------- fp32 -> fp16 converter (grid-stride, coalesced) ---------
__global__ void cvt_f16(const float* __restrict__ src, __half* __restrict__ dst,
                        size_t n) {
    size_t i = (size_t)blockIdx.x * blockDim.x + threadIdx.x;
    size_t stride = (size_t)gridDim.x * blockDim.x;
    for (; i < n; i += stride) dst[i] = __float2half_rn(src[i]);
}

// ---------------- SGEMM (projections; C = A_gathered * B^T + b1 + b2) -----
#define BM 128
#define BN 128
#define BK 16
__global__ __launch_bounds__(256) void gemm_nt_bias(
    const float* __restrict__ A, const int* __restrict__ idx,
    const float* __restrict__ B,
    const float* __restrict__ bias1, const float* __restrict__ bias2,
    float* __restrict__ C, int M, int N, int K)
{
    __shared__ float As[BK][BM];
    __shared__ float Bs[BK][BN];

    const int bm = blockIdx.y * BM;
    const int bn = blockIdx.x * BN;
    const int tid = threadIdx.x;
    const int tx = tid & 15;
    const int ty = tid >> 4;

    const int lrow = tid >> 1;
    const int lk   = (tid & 1) * 8;

    const int gm = bm + lrow;
    const bool am = (gm < M);
    const int ar = am ? (idx ? idx[gm] : gm) : 0;
    const float* Arow = A + (size_t)ar * K;
    const float* Brow = B + (size_t)(bn + lrow) * K;

    float4 la0, la1, lb0, lb1;
    const float4 z4 = make_float4(0.f, 0.f, 0.f, 0.f);
    la0 = am ? *(const float4*)(Arow + lk)     : z4;
    la1 = am ? *(const float4*)(Arow + lk + 4) : z4;
    lb0 = *(const float4*)(Brow + lk);
    lb1 = *(const float4*)(Brow + lk + 4);

    float acc[8][8];
#pragma unroll
    for (int i = 0; i < 8; i++)
#pragma unroll
        for (int j = 0; j < 8; j++) acc[i][j] = 0.f;

    for (int k0 = 0; k0 < K; k0 += BK) {
        As[lk + 0][lrow] = la0.x; As[lk + 1][lrow] = la0.y;
        As[lk + 2][lrow] = la0.z; As[lk + 3][lrow] = la0.w;
        As[lk + 4][lrow] = la1.x; As[lk + 5][lrow] = la1.y;
        As[lk + 6][lrow] = la1.z; As[lk + 7][lrow] = la1.w;
        Bs[lk + 0][lrow] = lb0.x; Bs[lk + 1][lrow] = lb0.y;
        Bs[lk + 2][lrow] = lb0.z; Bs[lk + 3][lrow] = lb0.w;
        Bs[lk + 4][lrow] = lb1.x; Bs[lk + 5][lrow] = lb1.y;
        Bs[lk + 6][lrow] = lb1.z; Bs[lk + 7][lrow] = lb1.w;
        __syncthreads();

        if (k0 + BK < K) {
            const int ko = k0 + BK + lk;
            la0 = am ? *(const float4*)(Arow + ko)     : z4;
            la1 = am ? *(const float4*)(Arow + ko + 4) : z4;
            lb0 = *(const float4*)(Brow + ko);
            lb1 = *(const float4*)(Brow + ko + 4);
        }

#pragma unroll
        for (int k = 0; k < BK; k++) {
            float ra[8], rb[8];
            *(float4*)(ra)     = *(const float4*)&As[k][ty * 4];
            *(float4*)(ra + 4) = *(const float4*)&As[k][64 + ty * 4];
            *(float4*)(rb)     = *(const float4*)&Bs[k][tx * 4];
            *(float4*)(rb + 4) = *(const float4*)&Bs[k][64 + tx * 4];
#pragma unroll
            for (int i = 0; i < 8; i++)
#pragma unroll
                for (int j = 0; j < 8; j++)
                    acc[i][j] = fmaf(ra[i], rb[j], acc[i][j]);
        }
        __syncthreads();
    }

#pragma unroll
    for (int i = 0; i < 8; i++) {
        const int m = bm + ((i < 4) ? (ty * 4 + i) : (64 + ty * 4 + i - 4));
        if (m >= M) continue;
#pragma unroll
        for (int j = 0; j < 8; j++) {
            const int n = bn + ((j < 4) ? (tx * 4 + j) : (64 + tx * 4 + j - 4));
            float v = acc[i][j] + bias1[n];
            if (bias2) v += bias2[n];
            C[(size_t)m * N + n] = v;
        }
    }
}

// ---------------- chunked persistent LSTM (warp-per-segment) --------------
#define RB 128
#define RT 256

__device__ __forceinline__ float sigmoidf_acc(float x) {
    return 1.f / (1.f + expf(-x));
}

__global__ __launch_bounds__(RT) void lstm_chunk(
    const float* __restrict__ encW, const float* __restrict__ decW,
    const float* __restrict__ Xe,   const float* __restrict__ Xd,
    float* hbuf, float* __restrict__ c, float* __restrict__ hs,
    unsigned* flags, int gs0, int gs1)
{
    __shared__ __align__(16) float4 hsm4[HSZ / 4];
    __shared__ float part[8 * 32];

    const int tid  = threadIdx.x;
    const int lane = tid & 31;
    const int wid  = tid >> 5;
    const int u0   = blockIdx.x * 8;
    const int grow = (lane >> 3) * HSZ + u0 + (lane & 7);

    const bool encPhase = (gs0 < TSZ);
    const float* W  = encPhase ? encW : decW;
    const float* Xb = encPhase ? Xe : Xd;

    float4 wreg[32];
    {
        const float4* wsrc = (const float4*)(W + (size_t)grow * HSZ) + wid * 32;
#pragma unroll
        for (int k = 0; k < 32; k++) wreg[k] = __ldg(wsrc + k);
    }

    const bool owner = (wid == 0 && lane < 8);
    float creg = owner ? c[u0 + lane] : 0.f;

    for (int gs = gs0; gs < gs1; ++gs) {
        const int s = encPhase ? gs : gs - TSZ;
        const float* Xrow = Xb + (size_t)s * G4H;
        const float4* hin4 = (const float4*)(hbuf + (gs & 1) * HSZ);
        float*        hout = hbuf + ((gs & 1) ^ 1) * HSZ;

        if (tid < RB) {
            const unsigned target = (unsigned)gs;
            while (*((volatile unsigned*)&flags[tid * 8]) < target) { }
        }
        __syncthreads();

        hsm4[tid] = __ldcv(hin4 + tid);

        float x0 = 0.f, x1 = 0.f, x2 = 0.f, x3 = 0.f;
        if (owner) {
            const int u = u0 + lane;
            x0 = __ldg(Xrow + u);
            x1 = __ldg(Xrow + HSZ + u);
            x2 = __ldg(Xrow + 2 * HSZ + u);
            x3 = __ldg(Xrow + 3 * HSZ + u);
        }
        __syncthreads();

        const float4* hseg = hsm4 + wid * 32;
        float a0 = 0.f, a1 = 0.f, a2 = 0.f, a3 = 0.f;
#pragma unroll
        for (int k = 0; k < 32; k += 4) {
            const float4 h0 = hseg[k],     h1 = hseg[k + 1];
            const float4 h2 = hseg[k + 2], h3 = hseg[k + 3];
            a0 = fmaf(wreg[k].x,     h0.x, a0); a0 = fmaf(wreg[k].y,     h0.y, a0);
            a0 = fmaf(wreg[k].z,     h0.z, a0); a0 = fmaf(wreg[k].w,     h0.w, a0);
            a1 = fmaf(wreg[k + 1].x, h1.x, a1); a1 = fmaf(wreg[k + 1].y, h1.y, a1);
            a1 = fmaf(wreg[k + 1].z, h1.z, a1); a1 = fmaf(wreg[k + 1].w, h1.w, a1);
            a2 = fmaf(wreg[k + 2].x, h2.x, a2); a2 = fmaf(wreg[k + 2].y, h2.y, a2);
            a2 = fmaf(wreg[k + 2].z, h2.z, a2); a2 = fmaf(wreg[k + 2].w, h2.w, a2);
            a3 = fmaf(wreg[k + 3].x, h3.x, a3); a3 = fmaf(wreg[k + 3].y, h3.y, a3);
            a3 = fmaf(wreg[k + 3].z, h3.z, a3); a3 = fmaf(wreg[k + 3].w, h3.w, a3);
        }
        part[wid * 32 + lane] = (a0 + a1) + (a2 + a3);
        __syncthreads();

        if (wid == 0) {
            float r = part[lane];
#pragma unroll
            for (int w = 1; w < 8; w++) r += part[w * 32 + lane];
            const int du = lane & 7;
            const float vI = __shfl_sync(0xffffffffu, r, du);
            const float vF = __shfl_sync(0xffffffffu, r, du + 8);
            const float vG = __shfl_sync(0xffffffffu, r, du + 16);
            const float vO = __shfl_sync(0xffffffffu, r, du + 24);
            if (lane < 8) {
                const int u = u0 + lane;
                const float gi = sigmoidf_acc(vI + x0);
                const float gf = sigmoidf_acc(vF + x1);
                const float gg = tanhf(vG + x2);
                const float go = sigmoidf_acc(vO + x3);
                creg = fmaf(gf, creg, gi * gg);
                const float h = go * tanhf(creg);
                __stcg(hout + u, h);
                if (!encPhase) hs[(size_t)s * HSZ + u] = h;
                __threadfence();
            }
            __syncwarp();
            if (lane == 0)
                __stcg(&flags[blockIdx.x * 8], (unsigned)(gs + 1));
        }
    }

    if (owner) c[u0 + lane] = creg;
}

// ================= HMMA fp16 logits GEMM (mma.sync, NOT tcgen05) ==========
// out[M=4095, N=32000] = hs_f16 @ W_f16^T + out_b, fp32 accumulate.
// Block 256 thr (8 warps), tile 128x128, K-chunks of 32 halfs.
// Warp grid 2(m) x 4(n); warp tile 64x32 -> 4 m-frags x 4 n-frags.
// B fragment: NON-trans ldmatrix on Bs[n][k] (row-major [N][K] == col-major
// K x N, exactly what mma.row.col expects). Trans was the round-13 bug.
#define MMPAD 40    // smem halfs per row (80B stride -> conflict-free ldmatrix)

__device__ __forceinline__ uint32_t smem_u32(const void* p) {
    uint32_t a;
    asm("{ .reg .u64 t; cvta.to.shared.u64 t, %1; cvt.u32.u64 %0, t; }"
        : "=r"(a) : "l"(p));
    return a;
}

__global__ __launch_bounds__(256) void logits_hmma(
    const __half* __restrict__ Ah,   // [M, 1024] fp16 hs
    const __half* __restrict__ Bh,   // [32000, 1024] fp16 out_W
    const float* __restrict__ bias,  // [32000]
    float* __restrict__ out, int M)
{
    __shared__ __half As[128][MMPAD];
    __shared__ __half Bs[128][MMPAD];

    const int tid  = threadIdx.x;
    const int lane = tid & 31;
    const int wid  = tid >> 5;
    const int wm   = wid >> 2;        // 0..1  (m)
    const int wn   = wid & 3;         // 0..3  (n)
    const int bm = blockIdx.y * 128;
    const int bn = blockIdx.x * 128;

    float acc[4][4][4];
#pragma unroll
    for (int i = 0; i < 4; i++)
#pragma unroll
        for (int j = 0; j < 4; j++)
#pragma unroll
            for (int k = 0; k < 4; k++) acc[i][j][k] = 0.f;

    for (int kc = 0; kc < HSZ / 32; ++kc) {
#pragma unroll
        for (int g = 0; g < 2; ++g) {
            const int idx = tid + g * 256;
            const int row = idx >> 2, c8 = idx & 3;
            const int gm = bm + row;
            uint4 av = make_uint4(0u, 0u, 0u, 0u);
            if (gm < M)
                av = *(const uint4*)(Ah + (size_t)gm * HSZ + kc * 32 + c8 * 8);
            *(uint4*)&As[row][c8 * 8] = av;
            const uint4 bv = *(const uint4*)(Bh + (size_t)(bn + row) * HSZ
                                             + kc * 32 + c8 * 8);
            *(uint4*)&Bs[row][c8 * 8] = bv;
        }
        __syncthreads();

#pragma unroll
        for (int ks = 0; ks < 2; ++ks) {           // two k16 steps
            // A fragments (4 m-frags of 16 rows), non-trans x4
            uint32_t af[4][4];
#pragma unroll
            for (int mf = 0; mf < 4; ++mf) {
                const int arow = wm * 64 + mf * 16 + (lane & 15);
                const int acol = ks * 16 + (lane >> 4) * 8;
                const uint32_t addr = smem_u32(&As[arow][acol]);
                asm volatile(
                    "ldmatrix.sync.aligned.m8n8.x4.shared.b16 {%0,%1,%2,%3}, [%4];"
                    : "=r"(af[mf][0]), "=r"(af[mf][1]),
                      "=r"(af[mf][2]), "=r"(af[mf][3]) : "r"(addr));
            }
            // B fragments (4 n-frags of 8 rows), NON-trans x2:
            // matrix0 = rows n0..n0+7 at k0 (reg0: k-lo), matrix1 same rows
            // at k0+8 (reg1: k-hi) — matches mma's {b0,b1},{b2,b3}.
            uint32_t bf[4][2];
#pragma unroll
            for (int nf = 0; nf < 4; ++nf) {
                const int l8 = lane & 15;
                const int brow = wn * 32 + nf * 8 + (l8 & 7);
                const int bcol = ks * 16 + (l8 >> 3) * 8;
                const uint32_t addr = smem_u32(&Bs[brow][bcol]);
                asm volatile(
                    "ldmatrix.sync.aligned.m8n8.x2.shared.b16 {%0,%1}, [%2];"
                    : "=r"(bf[nf][0]), "=r"(bf[nf][1]) : "r"(addr));
            }
#pragma unroll
            for (int mf = 0; mf < 4; ++mf)
#pragma unroll
                for (int nf = 0; nf < 4; ++nf) {
                    asm volatile(
                        "mma.sync.aligned.m16n8k16.row.col.f32.f16.f16.f32 "
                        "{%0,%1,%2,%3}, {%4,%5,%6,%7}, {%8,%9}, {%0,%1,%2,%3};"
                        : "+f"(acc[mf][nf][0]), "+f"(acc[mf][nf][1]),
                          "+f"(acc[mf][nf][2]), "+f"(acc[mf][nf][3])
                        : "r"(af[mf][0]), "r"(af[mf][1]),
                          "r"(af[mf][2]), "r"(af[mf][3]),
                          "r"(bf[nf][0]), "r"(bf[nf][1]));
                }
        }
        __syncthreads();
    }

    // epilogue: lane l -> rows l/4 (+8), cols (l%4)*2
#pragma unroll
    for (int mf = 0; mf < 4; ++mf) {
#pragma unroll
        for (int half = 0; half < 2; ++half) {
            const int m = bm + wm * 64 + mf * 16 + (lane >> 2) + half * 8;
            if (m >= M) continue;
            float* orow = out + (size_t)m * VSZ;
#pragma unroll
            for (int nf = 0; nf < 4; ++nf) {
                const int n = bn + wn * 32 + nf * 8 + (lane & 3) * 2;
                const float b0 = __ldg(bias + n);
                const float b1 = __ldg(bias + n + 1);
                float2 v;
                v.x = acc[mf][nf][half * 2 + 0] + b0;
                v.y = acc[mf][nf][half * 2 + 1] + b1;
                *(float2*)(orow + n) = v;
            }
        }
    }
}

// ---------------- launch ----------------
extern "C" void kernel_launch(void* const* d_in, const int* in_sizes, int n_in,
                              void* d_out, int out_size)
{
    const int*   seq     = (const int*)  d_in[0];
    const float* enc_emb = (const float*)d_in[1];
    const float* enc_Wih = (const float*)d_in[2];
    const float* enc_Whh = (const float*)d_in[3];
    const float* enc_bih = (const float*)d_in[4];
    const float* enc_bhh = (const float*)d_in[5];
    const float* dec_emb = (const float*)d_in[6];
    const float* dec_Wih = (const float*)d_in[7];
    const float* dec_Whh = (const float*)d_in[8];
    const float* dec_bih = (const float*)d_in[9];
    const float* dec_bhh = (const float*)d_in[10];
    const float* out_W   = (const float*)d_in[11];
    const float* out_b   = (const float*)d_in[12];
    float* out = (float*)d_out;

    void *pXenc = nullptr, *pXdec = nullptr, *phs = nullptr, *phsh = nullptr,
         *pWh = nullptr, *ph = nullptr, *pc = nullptr, *pflags = nullptr;
    cudaGetSymbolAddress(&pXenc, g_Xenc);
    cudaGetSymbolAddress(&pXdec, g_Xdec);
    cudaGetSymbolAddress(&phs,  g_hs);
    cudaGetSymbolAddress(&phsh, g_hsh);
    cudaGetSymbolAddress(&pWh,  g_Wh);
    cudaGetSymbolAddress(&ph,   g_h);
    cudaGetSymbolAddress(&pc,   g_c);
    cudaGetSymbolAddress(&pflags, g_flags);

    float* Xe   = (float*)pXenc;
    float* Xd   = (float*)pXdec;
    float* hs   = (float*)phs;
    __half* hsh = (__half*)phsh;
    __half* Wh  = (__half*)pWh;
    float* hbuf = (float*)ph;
    float* cst  = (float*)pc;
    unsigned* flags = (unsigned*)pflags;

    // 0) reset state every launch (graph-replay safe)
    init_kernel<<<4, 256>>>(hbuf, hbuf + HSZ, cst, flags);

    // 0b) convert out_W to fp16 (independent of everything else)
    cvt_f16<<<512, 256>>>(out_W, Wh, (size_t)VSZ * HSZ);

    // 1) encoder input projection
    {
        dim3 grid(G4H / BN, (TSZ + BM - 1) / BM);
        gemm_nt_bias<<<grid, 256>>>(enc_emb, seq, enc_Wih, enc_bih, enc_bhh,
                                    Xe, TSZ, G4H, ESZ);
    }
    // 2) decoder input projection (seq[:-1])
    {
        dim3 grid(G4H / BN, (TSZ - 1 + BM - 1) / BM);
        gemm_nt_bias<<<grid, 256>>>(dec_emb, seq, dec_Wih, dec_bih, dec_bhh,
                                    Xd, TSZ - 1, G4H, ESZ);
    }

    // 3) recurrence: 8 chunked persistent launches
    const int total_steps = TSZ + (TSZ - 1);   // 8191
    const int CHUNK = 1024;
    for (int gs0 = 0; gs0 < total_steps; gs0 += CHUNK) {
        int gs1 = gs0 + CHUNK;
        if (gs1 > total_steps) gs1 = total_steps;
        lstm_chunk<<<RB, RT>>>(enc_Whh, dec_Whh, Xe, Xd,
                               hbuf, cst, hs, flags, gs0, gs1);
    }

    // 3b) convert hs to fp16
    cvt_f16<<<512, 256>>>(hs, hsh, (size_t)(TSZ - 1) * HSZ);

    // 4) logits via HMMA fp16 mma.sync: out = hs @ out_W^T + out_b
    {
        dim3 grid(VSZ / 128, (TSZ - 1 + 127) / 128);   // 250 x 32
        logits_hmma<<<grid, 256>>>(hsh, Wh, out_b, out, TSZ - 1);
    }
}

// round 16
// speedup vs baseline: 4.1789x; 1.4235x over previous
#include <cuda_runtime.h>
#include <cuda_bf16.h>
#include <cuda_fp16.h>
#include <math.h>
#include <stdint.h>

// Problem constants  (V, E, H, T = 32000, 512, 1024, 4096)
#define VSZ 32000
#define ESZ 512
#define HSZ 1024
#define TSZ 4096
#define G4H 4096             // 4*H

// ---------------- scratch (device globals; no allocations) ----------------
__device__ float g_Xenc[(size_t)TSZ * G4H];        // 64 MB
__device__ float g_Xdec[(size_t)(TSZ - 1) * G4H];  // 64 MB
__device__ float g_hs[(size_t)(TSZ - 1) * HSZ];    // 16 MB
__device__ __half g_hsh[(size_t)(TSZ - 1) * HSZ];  // 8.4 MB fp16 hs
__device__ __half g_Wh [(size_t)VSZ * HSZ];        // 64 MB fp16 out_W
__device__ float g_c[HSZ];
// h broadcast records: 2 parity buffers x 384 records x 16B.
// record r (owner=r/3, sub=r%3) = {h[owner*8+sub*3], h[+1], h[+2], tag}
__device__ uint4 g_rec[2 * 384];

// ---------------- init: zero c + seed records ----------
__global__ void init_kernel(float* c, uint4* rec) {
    int tid = blockIdx.x * blockDim.x + threadIdx.x;
    if (tid < HSZ) c[tid] = 0.f;
    if (tid < 384) {
        rec[tid]       = make_uint4(0u, 0u, 0u, 0u);           // step 0: h=0
        rec[384 + tid] = make_uint4(0u, 0u, 0u, 0xFFFFFFFFu);
    }
}

// ---------------- fp32 -> fp16 converter ----------------------------------
__global__ void cvt_f16(const float* __restrict__ src, __half* __restrict__ dst,
                        size_t n) {
    size_t i = (size_t)blockIdx.x * blockDim.x + threadIdx.x;
    size_t stride = (size_t)gridDim.x * blockDim.x;
    for (; i < n; i += stride) dst[i] = __float2half_rn(src[i]);
}

// ---------------- SGEMM (projections; C = A_gathered * B^T + b1 + b2) -----
#define BM 128
#define BN 128
#define BK 16
__global__ __launch_bounds__(256) void gemm_nt_bias(
    const float* __restrict__ A, const int* __restrict__ idx,
    const float* __restrict__ B,
    const float* __restrict__ bias1, const float* __restrict__ bias2,
    float* __restrict__ C, int M, int N, int K)
{
    __shared__ float As[BK][BM];
    __shared__ float Bs[BK][BN];

    const int bm = blockIdx.y * BM;
    const int bn = blockIdx.x * BN;
    const int tid = threadIdx.x;
    const int tx = tid & 15;
    const int ty = tid >> 4;

    const int lrow = tid >> 1;
    const int lk   = (tid & 1) * 8;

    const int gm = bm + lrow;
    const bool am = (gm < M);
    const int ar = am ? (idx ? idx[gm] : gm) : 0;
    const float* Arow = A + (size_t)ar * K;
    const float* Brow = B + (size_t)(bn + lrow) * K;

    float4 la0, la1, lb0, lb1;
    const float4 z4 = make_float4(0.f, 0.f, 0.f, 0.f);
    la0 = am ? *(const float4*)(Arow + lk)     : z4;
    la1 = am ? *(const float4*)(Arow + lk + 4) : z4;
    lb0 = *(const float4*)(Brow + lk);
    lb1 = *(const float4*)(Brow + lk + 4);

    float acc[8][8];
#pragma unroll
    for (int i = 0; i < 8; i++)
#pragma unroll
        for (int j = 0; j < 8; j++) acc[i][j] = 0.f;

    for (int k0 = 0; k0 < K; k0 += BK) {
        As[lk + 0][lrow] = la0.x; As[lk + 1][lrow] = la0.y;
        As[lk + 2][lrow] = la0.z; As[lk + 3][lrow] = la0.w;
        As[lk + 4][lrow] = la1.x; As[lk + 5][lrow] = la1.y;
        As[lk + 6][lrow] = la1.z; As[lk + 7][lrow] = la1.w;
        Bs[lk + 0][lrow] = lb0.x; Bs[lk + 1][lrow] = lb0.y;
        Bs[lk + 2][lrow] = lb0.z; Bs[lk + 3][lrow] = lb0.w;
        Bs[lk + 4][lrow] = lb1.x; Bs[lk + 5][lrow] = lb1.y;
        Bs[lk + 6][lrow] = lb1.z; Bs[lk + 7][lrow] = lb1.w;
        __syncthreads();

        if (k0 + BK < K) {
            const int ko = k0 + BK + lk;
            la0 = am ? *(const float4*)(Arow + ko)     : z4;
            la1 = am ? *(const float4*)(Arow + ko + 4) : z4;
            lb0 = *(const float4*)(Brow + ko);
            lb1 = *(const float4*)(Brow + ko + 4);
        }

#pragma unroll
        for (int k = 0; k < BK; k++) {
            float ra[8], rb[8];
            *(float4*)(ra)     = *(const float4*)&As[k][ty * 4];
            *(float4*)(ra + 4) = *(const float4*)&As[k][64 + ty * 4];
            *(float4*)(rb)     = *(const float4*)&Bs[k][tx * 4];
            *(float4*)(rb + 4) = *(const float4*)&Bs[k][64 + tx * 4];
#pragma unroll
            for (int i = 0; i < 8; i++)
#pragma unroll
                for (int j = 0; j < 8; j++)
                    acc[i][j] = fmaf(ra[i], rb[j], acc[i][j]);
        }
        __syncthreads();
    }

#pragma unroll
    for (int i = 0; i < 8; i++) {
        const int m = bm + ((i < 4) ? (ty * 4 + i) : (64 + ty * 4 + i - 4));
        if (m >= M) continue;
#pragma unroll
        for (int j = 0; j < 8; j++) {
            const int n = bn + ((j < 4) ? (tx * 4 + j) : (64 + tx * 4 + j - 4));
            float v = acc[i][j] + bias1[n];
            if (bias2) v += bias2[n];
            C[(size_t)m * N + n] = v;
        }
    }
}

// ---------------- chunked persistent LSTM (fused tag+data handoff) --------
#define RB 128
#define RT 256

__device__ __forceinline__ uint4 ldcv4(const uint4* p) {
    uint4 v;
    asm volatile("ld.global.cv.v4.u32 {%0,%1,%2,%3}, [%4];"
                 : "=r"(v.x), "=r"(v.y), "=r"(v.z), "=r"(v.w)
                 : "l"(p) : "memory");
    return v;
}
__device__ __forceinline__ void stcg4(uint4* p, uint4 v) {
    asm volatile("st.global.cg.v4.u32 [%0], {%1,%2,%3,%4};"
                 :: "l"(p), "r"(v.x), "r"(v.y), "r"(v.z), "r"(v.w)
                 : "memory");
}
__device__ __forceinline__ float fsig(float x) {
    return __fdividef(1.f, 1.f + __expf(-x));
}
__device__ __forceinline__ float ftanh(float x) {
    return 1.f - __fdividef(2.f, __expf(2.f * x) + 1.f);
}

__global__ __launch_bounds__(RT) void lstm_chunk(
    const float* __restrict__ encW, const float* __restrict__ decW,
    const float* __restrict__ Xe,   const float* __restrict__ Xd,
    float* __restrict__ c, float* __restrict__ hs,
    uint4* rec, int gs0, int gs1)
{
    __shared__ __align__(16) float hsm[HSZ];
    __shared__ float part[8 * 32];

    const int tid  = threadIdx.x;
    const int lane = tid & 31;
    const int wid  = tid >> 5;
    const int u0   = blockIdx.x * 8;
    const int grow = (lane >> 3) * HSZ + u0 + (lane & 7);

    const bool encPhase = (gs0 < TSZ);        // chunk is single-phase
    const float* W  = encPhase ? encW : decW;
    const float* Xb = encPhase ? Xe : Xd;

    // weight slice in registers: row grow, cols [wid*128, +128)
    float4 wreg[32];
    {
        const float4* wsrc = (const float4*)(W + (size_t)grow * HSZ) + wid * 32;
#pragma unroll
        for (int k = 0; k < 32; k++) wreg[k] = __ldg(wsrc + k);
    }

    const bool owner = (wid == 0 && lane < 8);
    float creg = owner ? c[u0 + lane] : 0.f;

    for (int gs = gs0; gs < gs1; ++gs) {
        const int s = encPhase ? gs : gs - TSZ;
        const float* Xrow = Xb + (size_t)s * G4H;
        const uint4* rb = rec + (gs & 1) * 384;
        uint4*       wb = rec + ((gs & 1) ^ 1) * 384;

        // owners issue X loads first (independent of step data)
        float x0 = 0.f, x1 = 0.f, x2 = 0.f, x3 = 0.f;
        if (owner) {
            const int u = u0 + lane;
            x0 = __ldg(Xrow + u);
            x1 = __ldg(Xrow + HSZ + u);
            x2 = __ldg(Xrow + 2 * HSZ + u);
            x3 = __ldg(Xrow + 3 * HSZ + u);
        }

        // fused poll+fetch: thread t<192 owns records 2t, 2t+1
        if (tid < 192) {
            const int r0i = 2 * tid, r1i = 2 * tid + 1;
            uint4 a, b;
            bool da = false, db = false;
            do {
                if (!da) { a = ldcv4(rb + r0i); da = (a.w == (unsigned)gs); }
                if (!db) { b = ldcv4(rb + r1i); db = (b.w == (unsigned)gs); }
            } while (!(da && db));
            {   // stage record r0i
                const int own = r0i / 3, sub = r0i - own * 3;
                const int u = own * 8 + sub * 3;
                hsm[u]     = __uint_as_float(a.x);
                hsm[u + 1] = __uint_as_float(a.y);
                if (sub < 2) hsm[u + 2] = __uint_as_float(a.z);
            }
            {   // stage record r1i
                const int own = r1i / 3, sub = r1i - own * 3;
                const int u = own * 8 + sub * 3;
                hsm[u]     = __uint_as_float(b.x);
                hsm[u + 1] = __uint_as_float(b.y);
                if (sub < 2) hsm[u + 2] = __uint_as_float(b.z);
            }
        }
        __syncthreads();

        // dot: all lanes of warp `wid` read the SAME hseg[k] -> broadcast
        const float4* hseg = (const float4*)hsm + wid * 32;
        float a0 = 0.f, a1 = 0.f, a2 = 0.f, a3 = 0.f;
#pragma unroll
        for (int k = 0; k < 32; k += 4) {
            const float4 h0 = hseg[k],     h1 = hseg[k + 1];
            const float4 h2 = hseg[k + 2], h3 = hseg[k + 3];
            a0 = fmaf(wreg[k].x,     h0.x, a0); a0 = fmaf(wreg[k].y,     h0.y, a0);
            a0 = fmaf(wreg[k].z,     h0.z, a0); a0 = fmaf(wreg[k].w,     h0.w, a0);
            a1 = fmaf(wreg[k + 1].x, h1.x, a1); a1 = fmaf(wreg[k + 1].y, h1.y, a1);
            a1 = fmaf(wreg[k + 1].z, h1.z, a1); a1 = fmaf(wreg[k + 1].w, h1.w, a1);
            a2 = fmaf(wreg[k + 2].x, h2.x, a2); a2 = fmaf(wreg[k + 2].y, h2.y, a2);
            a2 = fmaf(wreg[k + 2].z, h2.z, a2); a2 = fmaf(wreg[k + 2].w, h2.w, a2);
            a3 = fmaf(wreg[k + 3].x, h3.x, a3); a3 = fmaf(wreg[k + 3].y, h3.y, a3);
            a3 = fmaf(wreg[k + 3].z, h3.z, a3); a3 = fmaf(wreg[k + 3].w, h3.w, a3);
        }
        part[wid * 32 + lane] = (a0 + a1) + (a2 + a3);
        __syncthreads();

        // warp 0: finish rows, compute gates, publish records
        if (wid == 0) {
            float r = part[lane];
#pragma unroll
            for (int w = 1; w < 8; w++) r += part[w * 32 + lane];
            const int du = lane & 7;
            const float vI = __shfl_sync(0xffffffffu, r, du);
            const float vF = __shfl_sync(0xffffffffu, r, du + 8);
            const float vG = __shfl_sync(0xffffffffu, r, du + 16);
            const float vO = __shfl_sync(0xffffffffu, r, du + 24);
            float hval = 0.f;
            if (lane < 8) {
                const float gi = fsig(vI + x0);
                const float gf = fsig(vF + x1);
                const float gg = ftanh(vG + x2);
                const float go = fsig(vO + x3);
                creg = fmaf(gf, creg, gi * gg);
                hval = go * ftanh(creg);
                if (!encPhase) hs[(size_t)s * HSZ + (u0 + lane)] = hval;
            }
            // pack 3 records: {h3r, h3r+1, h3r+2, tag} (tag rides WITH data;
            // a 16B aligned store is a single transaction -> no fence needed)
            const float v0 = __shfl_sync(0xffffffffu, hval, (lane * 3) & 31);
            const float v1 = __shfl_sync(0xffffffffu, hval, (lane * 3 + 1) & 31);
            const float v2 = __shfl_sync(0xffffffffu, hval, (lane * 3 + 2) & 31);
            if (lane < 3) {
                uint4 rv;
                rv.x = __float_as_uint(v0);
                rv.y = __float_as_uint(v1);
                rv.z = __float_as_uint(v2);
                rv.w = (unsigned)(gs + 1);
                stcg4(wb + blockIdx.x * 3 + lane, rv);
            }
        }
        // no trailing sync: next iteration's poll gates progress; the record
        // store depends (dataflow) on this step's fully-staged h.
    }

    if (owner) c[u0 + lane] = creg;
}

// ================= HMMA fp16 logits GEMM (mma.sync) ========================
#define MMPAD 40

__device__ __forceinline__ uint32_t smem_u32(const void* p) {
    uint32_t a;
    asm("{ .reg .u64 t; cvta.to.shared.u64 t, %1; cvt.u32.u64 %0, t; }"
        : "=r"(a) : "l"(p));
    return a;
}

__global__ __launch_bounds__(256) void logits_hmma(
    const __half* __restrict__ Ah,   // [M, 1024] fp16 hs
    const __half* __restrict__ Bh,   // [32000, 1024] fp16 out_W
    const float* __restrict__ bias,  // [32000]
    float* __restrict__ out, int M)
{
    __shared__ __half As[128][MMPAD];
    __shared__ __half Bs[128][MMPAD];

    const int tid  = threadIdx.x;
    const int lane = tid & 31;
    const int wid  = tid >> 5;
    const int wm   = wid >> 2;
    const int wn   = wid & 3;
    const int bm = blockIdx.y * 128;
    const int bn = blockIdx.x * 128;

    float acc[4][4][4];
#pragma unroll
    for (int i = 0; i < 4; i++)
#pragma unroll
        for (int j = 0; j < 4; j++)
#pragma unroll
            for (int k = 0; k < 4; k++) acc[i][j][k] = 0.f;

    for (int kc = 0; kc < HSZ / 32; ++kc) {
#pragma unroll
        for (int g = 0; g < 2; ++g) {
            const int idx = tid + g * 256;
            const int row = idx >> 2, c8 = idx & 3;
            const int gm = bm + row;
            uint4 av = make_uint4(0u, 0u, 0u, 0u);
            if (gm < M)
                av = *(const uint4*)(Ah + (size_t)gm * HSZ + kc * 32 + c8 * 8);
            *(uint4*)&As[row][c8 * 8] = av;
            const uint4 bv = *(const uint4*)(Bh + (size_t)(bn + row) * HSZ
                                             + kc * 32 + c8 * 8);
            *(uint4*)&Bs[row][c8 * 8] = bv;
        }
        __syncthreads();

#pragma unroll
        for (int ks = 0; ks < 2; ++ks) {
            uint32_t af[4][4];
#pragma unroll
            for (int mf = 0; mf < 4; ++mf) {
                const int arow = wm * 64 + mf * 16 + (lane & 15);
                const int acol = ks * 16 + (lane >> 4) * 8;
                const uint32_t addr = smem_u32(&As[arow][acol]);
                asm volatile(
                    "ldmatrix.sync.aligned.m8n8.x4.shared.b16 {%0,%1,%2,%3}, [%4];"
                    : "=r"(af[mf][0]), "=r"(af[mf][1]),
                      "=r"(af[mf][2]), "=r"(af[mf][3]) : "r"(addr));
            }
            uint32_t bf[4][2];
#pragma unroll
            for (int nf = 0; nf < 4; ++nf) {
                const int l8 = lane & 15;
                const int brow = wn * 32 + nf * 8 + (l8 & 7);
                const int bcol = ks * 16 + (l8 >> 3) * 8;
                const uint32_t addr = smem_u32(&Bs[brow][bcol]);
                asm volatile(
                    "ldmatrix.sync.aligned.m8n8.x2.shared.b16 {%0,%1}, [%2];"
                    : "=r"(bf[nf][0]), "=r"(bf[nf][1]) : "r"(addr));
            }
#pragma unroll
            for (int mf = 0; mf < 4; ++mf)
#pragma unroll
                for (int nf = 0; nf < 4; ++nf) {
                    asm volatile(
                        "mma.sync.aligned.m16n8k16.row.col.f32.f16.f16.f32 "
                        "{%0,%1,%2,%3}, {%4,%5,%6,%7}, {%8,%9}, {%0,%1,%2,%3};"
                        : "+f"(acc[mf][nf][0]), "+f"(acc[mf][nf][1]),
                          "+f"(acc[mf][nf][2]), "+f"(acc[mf][nf][3])
                        : "r"(af[mf][0]), "r"(af[mf][1]),
                          "r"(af[mf][2]), "r"(af[mf][3]),
                          "r"(bf[nf][0]), "r"(bf[nf][1]));
                }
        }
        __syncthreads();
    }

#pragma unroll
    for (int mf = 0; mf < 4; ++mf) {
#pragma unroll
        for (int half = 0; half < 2; ++half) {
            const int m = bm + wm * 64 + mf * 16 + (lane >> 2) + half * 8;
            if (m >= M) continue;
            float* orow = out + (size_t)m * VSZ;
#pragma unroll
            for (int nf = 0; nf < 4; ++nf) {
                const int n = bn + wn * 32 + nf * 8 + (lane & 3) * 2;
                const float b0 = __ldg(bias + n);
                const float b1 = __ldg(bias + n + 1);
                float2 v;
                v.x = acc[mf][nf][half * 2 + 0] + b0;
                v.y = acc[mf][nf][half * 2 + 1] + b1;
                *(float2*)(orow + n) = v;
            }
        }
    }
}

// ---------------- launch ----------------
extern "C" void kernel_launch(void* const* d_in, const int* in_sizes, int n_in,
                              void* d_out, int out_size)
{
    const int*   seq     = (const int*)  d_in[0];
    const float* enc_emb = (const float*)d_in[1];
    const float* enc_Wih = (const float*)d_in[2];
    const float* enc_Whh = (const float*)d_in[3];
    const float* enc_bih = (const float*)d_in[4];
    const float* enc_bhh = (const float*)d_in[5];
    const float* dec_emb = (const float*)d_in[6];
    const float* dec_Wih = (const float*)d_in[7];
    const float* dec_Whh = (const float*)d_in[8];
    const float* dec_bih = (const float*)d_in[9];
    const float* dec_bhh = (const float*)d_in[10];
    const float* out_W   = (const float*)d_in[11];
    const float* out_b   = (const float*)d_in[12];
    float* out = (float*)d_out;

    void *pXenc = nullptr, *pXdec = nullptr, *phs = nullptr, *phsh = nullptr,
         *pWh = nullptr, *pc = nullptr, *prec = nullptr;
    cudaGetSymbolAddress(&pXenc, g_Xenc);
    cudaGetSymbolAddress(&pXdec, g_Xdec);
    cudaGetSymbolAddress(&phs,  g_hs);
    cudaGetSymbolAddress(&phsh, g_hsh);
    cudaGetSymbolAddress(&pWh,  g_Wh);
    cudaGetSymbolAddress(&pc,   g_c);
    cudaGetSymbolAddress(&prec, g_rec);

    float* Xe   = (float*)pXenc;
    float* Xd   = (float*)pXdec;
    float* hs   = (float*)phs;
    __half* hsh = (__half*)phsh;
    __half* Wh  = (__half*)pWh;
    float* cst  = (float*)pc;
    uint4* rec  = (uint4*)prec;

    // 0) reset state every launch (graph-replay safe)
    init_kernel<<<4, 256>>>(cst, rec);

    // 0b) convert out_W to fp16
    cvt_f16<<<512, 256>>>(out_W, Wh, (size_t)VSZ * HSZ);

    // 1) encoder input projection
    {
        dim3 grid(G4H / BN, (TSZ + BM - 1) / BM);
        gemm_nt_bias<<<grid, 256>>>(enc_emb, seq, enc_Wih, enc_bih, enc_bhh,
                                    Xe, TSZ, G4H, ESZ);
    }
    // 2) decoder input projection (seq[:-1])
    {
        dim3 grid(G4H / BN, (TSZ - 1 + BM - 1) / BM);
        gemm_nt_bias<<<grid, 256>>>(dec_emb, seq, dec_Wih, dec_bih, dec_bhh,
                                    Xd, TSZ - 1, G4H, ESZ);
    }

    // 3) recurrence: 8 chunked persistent launches
    const int total_steps = TSZ + (TSZ - 1);   // 8191
    const int CHUNK = 1024;
    for (int gs0 = 0; gs0 < total_steps; gs0 += CHUNK) {
        int gs1 = gs0 + CHUNK;
        if (gs1 > total_steps) gs1 = total_steps;
        lstm_chunk<<<RB, RT>>>(enc_Whh, dec_Whh, Xe, Xd,
                               cst, hs, rec, gs0, gs1);
    }

    // 3b) convert hs to fp16
    cvt_f16<<<512, 256>>>(hs, hsh, (size_t)(TSZ - 1) * HSZ);

    // 4) logits via HMMA fp16 mma.sync: out = hs @ out_W^T + out_b
    {
        dim3 grid(VSZ / 128, (TSZ - 1 + 127) / 128);   // 250 x 32
        logits_hmma<<<grid, 256>>>(hsh, Wh, out_b, out, TSZ - 1);
    }
}